// round 4
// baseline (speedup 1.0000x reference)
#include <cuda_runtime.h>
#include <math.h>

#define NN 50000
#define EE 800000
#define RR 8
#define BB 4
#define NB ((NN + 255) / 256)

// ---------------- scratch (device globals; no allocation) ----------------
__device__ float g_x1[NN * 64];
__device__ float g_x2[NN * 128];
__device__ float g_x3[NN * 32];
__device__ float g_h[NN * 128];
__device__ float g_al[NN * 8];
__device__ int   g_cnt[NN * RR];
__device__ int   g_row_off[NN + 1];
__device__ int   g_cursor[NN];
__device__ int   g_adj[EE];            // src | (etype<<16)
__device__ int   g_pos[EE];
__device__ float g_ev[(size_t)EE * 4]; // CSR-ordered softmax numerators
__device__ int   g_nodescan[NN];
__device__ int   g_blocksum[NB];
__device__ int   g_blockoff[NB];

__device__ __forceinline__ float4 ld4(const float* p) { return __ldg((const float4*)p); }

// ---------------- CSR build ----------------
__global__ void zero_int(int* __restrict__ p, int n) {
    int i = blockIdx.x * blockDim.x + threadIdx.x;
    if (i < n) p[i] = 0;
}

__global__ void hist_kernel(const int* __restrict__ dst, const int* __restrict__ et) {
    int e = blockIdx.x * blockDim.x + threadIdx.x;
    if (e < EE) atomicAdd(&g_cnt[dst[e] * RR + et[e]], 1);
}

__global__ void scanA() {
    __shared__ int sh[256];
    int t = threadIdx.x;
    int n = blockIdx.x * 256 + t;
    int deg = 0;
    if (n < NN) {
#pragma unroll
        for (int r = 0; r < RR; r++) deg += g_cnt[n * RR + r];
    }
    int val = deg;
    sh[t] = val;
    __syncthreads();
    for (int d = 1; d < 256; d <<= 1) {
        int a = (t >= d) ? sh[t - d] : 0;
        __syncthreads();
        val += a;
        sh[t] = val;
        __syncthreads();
    }
    if (n < NN) g_nodescan[n] = val - deg;
    if (t == 255) g_blocksum[blockIdx.x] = val;
}

__global__ void scanB() {
    __shared__ int sh[256];
    int t = threadIdx.x;
    int own = (t < NB) ? g_blocksum[t] : 0;
    int val = own;
    sh[t] = val;
    __syncthreads();
    for (int d = 1; d < 256; d <<= 1) {
        int a = (t >= d) ? sh[t - d] : 0;
        __syncthreads();
        val += a;
        sh[t] = val;
        __syncthreads();
    }
    if (t < NB) g_blockoff[t] = val - own;
    if (t == NB - 1) g_row_off[NN] = val;
}

__global__ void scanC() {
    int n = blockIdx.x * 256 + threadIdx.x;
    if (n < NN) {
        int off = g_blockoff[blockIdx.x] + g_nodescan[n];
        g_row_off[n] = off;
        g_cursor[n] = off;
    }
}

__global__ void fill_kernel(const int* __restrict__ src, const int* __restrict__ dst,
                            const int* __restrict__ et) {
    int e = blockIdx.x * blockDim.x + threadIdx.x;
    if (e < EE) {
        int d = dst[e];
        int pos = atomicAdd(&g_cursor[d], 1);
        g_adj[pos] = src[e] | (et[e] << 16);
        g_pos[e] = pos;
    }
}

// ---------------- RGCN: float4 gather (G edge-groups) + fused basis GEMM ----------------
template <int IN, int OUT, int G>
__global__ __launch_bounds__((IN / 4) * G) void rgcn_gather(
    const float* __restrict__ x, const float* __restrict__ basis,
    const float* __restrict__ comp, const float* __restrict__ root,
    const float* __restrict__ bias, float* __restrict__ out) {
    const int V = IN / 4;
    const int T = V * G;
    const int PART = T / OUT;
    __shared__ float4 red4[G * BB * V];
    __shared__ float zsh[BB * IN];
    __shared__ float xsh[IN];
    __shared__ float wsh[RR * BB];
    __shared__ float rsum[T];
    int n = blockIdx.x;
    int t = threadIdx.x;
    int g = t / V, i = t % V;

    if (t < RR) {
        float ic = 1.f / fmaxf((float)g_cnt[n * RR + t], 1.f);
#pragma unroll
        for (int b = 0; b < BB; b++) wsh[t * BB + b] = comp[t * BB + b] * ic;
    }
    if (t < IN) xsh[t] = x[(size_t)n * IN + t];
    __syncthreads();

    float4 acc[BB];
#pragma unroll
    for (int b = 0; b < BB; b++) acc[b] = make_float4(0.f, 0.f, 0.f, 0.f);

    int k1 = g_row_off[n + 1];
    int k = g_row_off[n] + g;
    for (; k + G < k1; k += 2 * G) {
        int va = g_adj[k], vb = g_adj[k + G];
        float4 xa = ld4(x + (size_t)(va & 0xFFFF) * IN + 4 * i);
        float4 xb = ld4(x + (size_t)(vb & 0xFFFF) * IN + 4 * i);
        const float* wa = wsh + (va >> 16) * BB;
        const float* wb = wsh + (vb >> 16) * BB;
#pragma unroll
        for (int b = 0; b < BB; b++) {
            acc[b].x += wa[b] * xa.x + wb[b] * xb.x;
            acc[b].y += wa[b] * xa.y + wb[b] * xb.y;
            acc[b].z += wa[b] * xa.z + wb[b] * xb.z;
            acc[b].w += wa[b] * xa.w + wb[b] * xb.w;
        }
    }
    if (k < k1) {
        int va = g_adj[k];
        float4 xa = ld4(x + (size_t)(va & 0xFFFF) * IN + 4 * i);
        const float* wa = wsh + (va >> 16) * BB;
#pragma unroll
        for (int b = 0; b < BB; b++) {
            acc[b].x += wa[b] * xa.x;
            acc[b].y += wa[b] * xa.y;
            acc[b].z += wa[b] * xa.z;
            acc[b].w += wa[b] * xa.w;
        }
    }
#pragma unroll
    for (int b = 0; b < BB; b++) red4[(g * BB + b) * V + i] = acc[b];
    __syncthreads();

    if (t < BB * V) {
        int b = t / V, ii = t % V;
        float4 s = red4[b * V + ii];
#pragma unroll
        for (int gg = 1; gg < G; gg++) {
            float4 v = red4[(gg * BB + b) * V + ii];
            s.x += v.x; s.y += v.y; s.z += v.z; s.w += v.w;
        }
        ((float4*)zsh)[b * V + ii] = s;
    }
    __syncthreads();

    int o = t % OUT, p = t / OUT;
    float a = 0.f;
    for (int kk = p; kk < BB * IN; kk += PART) a += zsh[kk] * __ldg(basis + kk * OUT + o);
    for (int kk = p; kk < IN; kk += PART) a += xsh[kk] * __ldg(root + kk * OUT + o);
    rsum[t] = a;
    __syncthreads();
    if (t < OUT) {
        float s = bias[t];
#pragma unroll
        for (int pp = 0; pp < PART; pp++) s += rsum[pp * OUT + t];
        out[(size_t)n * OUT + t] = fmaxf(s, 0.f);
    }
}

// ---------------- GAT node phase ----------------
template <int IN, int H, int C>
__global__ __launch_bounds__(H * C) void gat_node(
    const float* __restrict__ x, const float* __restrict__ w,
    const float* __restrict__ asrc, const float* __restrict__ adst) {
    const int OUT = H * C;
    __shared__ float xsh[IN];
    __shared__ float hsh[OUT];
    int n = blockIdx.x;
    int t = threadIdx.x;
    for (int i = t; i < IN; i += OUT) xsh[i] = x[(size_t)n * IN + i];
    __syncthreads();
    float a = 0.f;
#pragma unroll 4
    for (int i = 0; i < IN; i++) a += xsh[i] * w[i * OUT + t];
    hsh[t] = a;
    g_h[(size_t)n * OUT + t] = a;
    __syncthreads();
    if (t < 2 * H) {
        int hh = (t < H) ? t : t - H;
        const float* av = (t < H) ? asrc : adst;
        float s = 0.f;
#pragma unroll
        for (int c = 0; c < C; c++) s += hsh[hh * C + c] * av[hh * C + c];
        g_al[n * 2 * H + t] = s;
    }
}

// ---------------- per-edge softmax numerators ----------------
__device__ __forceinline__ float lrexp(float v) {
    v = v > 0.f ? v : 0.2f * v;
    return __expf(v);
}

__global__ void ev_kernel(const int* __restrict__ src, const int* __restrict__ dst) {
    int e = blockIdx.x * blockDim.x + threadIdx.x;
    if (e >= EE) return;
    int s = src[e], d = dst[e], pos = g_pos[e];
    float4 as = *(const float4*)(g_al + (size_t)s * 8);
    float4 ad = *(const float4*)(g_al + (size_t)d * 8 + 4);
    float4 ev;
    ev.x = lrexp(as.x + ad.x);
    ev.y = lrexp(as.y + ad.y);
    ev.z = lrexp(as.z + ad.z);
    ev.w = lrexp(as.w + ad.w);
    *(float4*)(g_ev + (size_t)pos * 4) = ev;
}

// ---------------- GAT gathers (float4, G edge-groups) ----------------
template <int H, int C, int G>
__global__ __launch_bounds__((H * C / 4) * G) void gat_gather_concat(
    const float* __restrict__ bias, float* __restrict__ out) {
    const int HC = H * C;
    const int V = HC / 4;        // float4 lanes per edge
    const int LPH = V / H;       // lanes per head
    __shared__ float4 red4[G * V];
    __shared__ float zred[G * H];
    int n = blockIdx.x;
    int t = threadIdx.x;
    int g = t / V, i = t % V;
    int h = i / LPH;

    float4 acc = make_float4(0.f, 0.f, 0.f, 0.f);
    float z = 0.f;
    int k1 = g_row_off[n + 1];
    int k = g_row_off[n] + g;
    for (; k + G < k1; k += 2 * G) {
        int sa = g_adj[k] & 0xFFFF, sb = g_adj[k + G] & 0xFFFF;
        float ea = __ldg(g_ev + (size_t)k * 4 + h);
        float eb = __ldg(g_ev + (size_t)(k + G) * 4 + h);
        float4 ha = ld4(g_h + (size_t)sa * HC + 4 * i);
        float4 hb = ld4(g_h + (size_t)sb * HC + 4 * i);
        z += ea + eb;
        acc.x += ea * ha.x + eb * hb.x;
        acc.y += ea * ha.y + eb * hb.y;
        acc.z += ea * ha.z + eb * hb.z;
        acc.w += ea * ha.w + eb * hb.w;
    }
    if (k < k1) {
        int sa = g_adj[k] & 0xFFFF;
        float ea = __ldg(g_ev + (size_t)k * 4 + h);
        float4 ha = ld4(g_h + (size_t)sa * HC + 4 * i);
        z += ea;
        acc.x += ea * ha.x; acc.y += ea * ha.y; acc.z += ea * ha.z; acc.w += ea * ha.w;
    }
    if (g == 0) {  // self loop
        float ev = lrexp(g_al[(size_t)n * 8 + h] + g_al[(size_t)n * 8 + 4 + h]);
        float4 hv = ld4(g_h + (size_t)n * HC + 4 * i);
        z += ev;
        acc.x += ev * hv.x; acc.y += ev * hv.y; acc.z += ev * hv.z; acc.w += ev * hv.w;
    }
    red4[g * V + i] = acc;
    if (i % LPH == 0) zred[g * H + h] = z;
    __syncthreads();

    if (t < V) {
        float4 s = red4[t];
        int hh = t / LPH;
        float zz = zred[hh];
#pragma unroll
        for (int gg = 1; gg < G; gg++) {
            float4 v = red4[gg * V + t];
            s.x += v.x; s.y += v.y; s.z += v.z; s.w += v.w;
            zz += zred[gg * H + hh];
        }
        float inv = 1.f / zz;
        float4 b = __ldg((const float4*)bias + t);
        float4 o;
        o.x = s.x * inv + b.x; o.y = s.y * inv + b.y;
        o.z = s.z * inv + b.z; o.w = s.w * inv + b.w;
        ((float4*)out)[(size_t)n * V + t] = o;
    }
}

template <int H, int C, int G>
__global__ __launch_bounds__((H * C / 4) * G) void gat_gather_mean_tanh(
    const float* __restrict__ bias, float* __restrict__ out) {
    const int HC = H * C;
    const int V = HC / 4;
    const int LPH = V / H;
    __shared__ float4 red4[G * V];
    __shared__ float zred[G * H];
    __shared__ float sh[HC];
    int n = blockIdx.x;
    int t = threadIdx.x;
    int g = t / V, i = t % V;
    int h = i / LPH;

    float4 acc = make_float4(0.f, 0.f, 0.f, 0.f);
    float z = 0.f;
    int k1 = g_row_off[n + 1];
    int k = g_row_off[n] + g;
    for (; k + G < k1; k += 2 * G) {
        int sa = g_adj[k] & 0xFFFF, sb = g_adj[k + G] & 0xFFFF;
        float ea = __ldg(g_ev + (size_t)k * 4 + h);
        float eb = __ldg(g_ev + (size_t)(k + G) * 4 + h);
        float4 ha = ld4(g_h + (size_t)sa * HC + 4 * i);
        float4 hb = ld4(g_h + (size_t)sb * HC + 4 * i);
        z += ea + eb;
        acc.x += ea * ha.x + eb * hb.x;
        acc.y += ea * ha.y + eb * hb.y;
        acc.z += ea * ha.z + eb * hb.z;
        acc.w += ea * ha.w + eb * hb.w;
    }
    if (k < k1) {
        int sa = g_adj[k] & 0xFFFF;
        float ea = __ldg(g_ev + (size_t)k * 4 + h);
        float4 ha = ld4(g_h + (size_t)sa * HC + 4 * i);
        z += ea;
        acc.x += ea * ha.x; acc.y += ea * ha.y; acc.z += ea * ha.z; acc.w += ea * ha.w;
    }
    if (g == 0) {
        float ev = lrexp(g_al[(size_t)n * 8 + h] + g_al[(size_t)n * 8 + 4 + h]);
        float4 hv = ld4(g_h + (size_t)n * HC + 4 * i);
        z += ev;
        acc.x += ev * hv.x; acc.y += ev * hv.y; acc.z += ev * hv.z; acc.w += ev * hv.w;
    }
    red4[g * V + i] = acc;
    if (i % LPH == 0) zred[g * H + h] = z;
    __syncthreads();

    if (t < V) {
        float4 s = red4[t];
        int hh = t / LPH;
        float zz = zred[hh];
#pragma unroll
        for (int gg = 1; gg < G; gg++) {
            float4 v = red4[gg * V + t];
            s.x += v.x; s.y += v.y; s.z += v.z; s.w += v.w;
            zz += zred[gg * H + hh];
        }
        float inv = 1.f / zz;
        sh[4 * t + 0] = s.x * inv;
        sh[4 * t + 1] = s.y * inv;
        sh[4 * t + 2] = s.z * inv;
        sh[4 * t + 3] = s.w * inv;
    }
    __syncthreads();
    if (t < C) {
        float s = 0.f;
#pragma unroll
        for (int hh = 0; hh < H; hh++) s += sh[hh * C + t];
        s = s * (1.f / H) + bias[t];
        s = fmaxf(s, 0.f);
        out[(size_t)n * C + t] = tanhf(s);
    }
}

// ---------------- launch ----------------
extern "C" void kernel_launch(void* const* d_in, const int* in_sizes, int n_in,
                              void* d_out, int out_size) {
    const float* x      = (const float*)d_in[0];
    const int*   ei     = (const int*)d_in[1];
    const int*   et     = (const int*)d_in[2];
    const float* basis1 = (const float*)d_in[3];
    const float* comp1  = (const float*)d_in[4];
    const float* root1  = (const float*)d_in[5];
    const float* brg1   = (const float*)d_in[6];
    const float* wg1    = (const float*)d_in[7];
    const float* asrc1  = (const float*)d_in[8];
    const float* adst1  = (const float*)d_in[9];
    const float* bg1    = (const float*)d_in[10];
    const float* basis2 = (const float*)d_in[11];
    const float* comp2  = (const float*)d_in[12];
    const float* root2  = (const float*)d_in[13];
    const float* brg2   = (const float*)d_in[14];
    const float* wg2    = (const float*)d_in[15];
    const float* asrc2  = (const float*)d_in[16];
    const float* adst2  = (const float*)d_in[17];
    const float* bg2    = (const float*)d_in[18];
    float* out = (float*)d_out;
    const int* src = ei;
    const int* dst = ei + EE;

    int* p_cnt;
    float *p_x1, *p_x2, *p_x3;
    cudaGetSymbolAddress((void**)&p_cnt, g_cnt);
    cudaGetSymbolAddress((void**)&p_x1, g_x1);
    cudaGetSymbolAddress((void**)&p_x2, g_x2);
    cudaGetSymbolAddress((void**)&p_x3, g_x3);

    // --- CSR build ---
    zero_int<<<(NN * RR + 255) / 256, 256>>>(p_cnt, NN * RR);
    hist_kernel<<<(EE + 255) / 256, 256>>>(dst, et);
    scanA<<<NB, 256>>>();
    scanB<<<1, 256>>>();
    scanC<<<NB, 256>>>();
    fill_kernel<<<(EE + 255) / 256, 256>>>(src, dst, et);

    // ---- RGCN 1: 64 -> 64, relu ----
    rgcn_gather<64, 64, 8><<<NN, 128>>>(x, basis1, comp1, root1, brg1, p_x1);
    // ---- GAT 1: 64 -> 4x32 concat ----
    gat_node<64, 4, 32><<<NN, 128>>>(p_x1, wg1, asrc1, adst1);
    ev_kernel<<<(EE + 255) / 256, 256>>>(src, dst);
    gat_gather_concat<4, 32, 8><<<NN, 256>>>(bg1, p_x2);
    // ---- RGCN 2: 128 -> 32, relu ----
    rgcn_gather<128, 32, 8><<<NN, 256>>>(p_x2, basis2, comp2, root2, brg2, p_x3);
    // ---- GAT 2: 32 -> 4x16, mean heads, relu, tanh ----
    gat_node<32, 4, 16><<<NN, 64>>>(p_x3, wg2, asrc2, adst2);
    ev_kernel<<<(EE + 255) / 256, 256>>>(src, dst);
    gat_gather_mean_tanh<4, 16, 8><<<NN, 128>>>(bg2, out);
}

// round 6
// speedup vs baseline: 1.3834x; 1.3834x over previous
#include <cuda_runtime.h>
#include <math.h>

#define NN 50000
#define EE 800000
#define RR 8
#define BB 4
#define NB ((NN + 255) / 256)

// ---------------- scratch (device globals; no allocation) ----------------
__device__ float g_x1[NN * 64];
__device__ float g_x2[NN * 128];
__device__ float g_x3[NN * 32];
__device__ float g_h[NN * 128];
__device__ float g_al[NN * 8];
__device__ int   g_cnt[NN * RR];
__device__ int   g_row_off[NN + 1];
__device__ int   g_cursor[NN];
__device__ int   g_adj[EE];            // src | (etype<<16)
__device__ int   g_pos[EE];
__device__ float g_ev[(size_t)EE * 4]; // CSR-ordered softmax numerators [pos][4]
__device__ int   g_nodescan[NN];
__device__ int   g_blocksum[NB];
__device__ int   g_blockoff[NB];

__device__ __forceinline__ float4 ld4(const float* p) { return __ldg((const float4*)p); }
__device__ __forceinline__ float2 ld2(const float* p) { return __ldg((const float2*)p); }

template <int VW>
__device__ __forceinline__ void ldv(float (&d)[VW], const float* p) {
    if (VW == 2) {
        float2 v = ld2(p);
        d[0] = v.x; d[1] = v.y;
    } else {
        float4 v = ld4(p);
        d[0] = v.x; d[1] = v.y; d[2] = v.z; d[3] = v.w;
    }
}

// ---------------- CSR build ----------------
__global__ void zero_int(int* __restrict__ p, int n) {
    int i = blockIdx.x * blockDim.x + threadIdx.x;
    if (i < n) p[i] = 0;
}

__global__ void hist_kernel(const int* __restrict__ dst, const int* __restrict__ et) {
    int e = blockIdx.x * blockDim.x + threadIdx.x;
    if (e < EE) atomicAdd(&g_cnt[dst[e] * RR + et[e]], 1);
}

__global__ void scanA() {
    __shared__ int sh[256];
    int t = threadIdx.x;
    int n = blockIdx.x * 256 + t;
    int deg = 0;
    if (n < NN) {
#pragma unroll
        for (int r = 0; r < RR; r++) deg += g_cnt[n * RR + r];
    }
    int val = deg;
    sh[t] = val;
    __syncthreads();
    for (int d = 1; d < 256; d <<= 1) {
        int a = (t >= d) ? sh[t - d] : 0;
        __syncthreads();
        val += a;
        sh[t] = val;
        __syncthreads();
    }
    if (n < NN) g_nodescan[n] = val - deg;
    if (t == 255) g_blocksum[blockIdx.x] = val;
}

__global__ void scanB() {
    __shared__ int sh[256];
    int t = threadIdx.x;
    int own = (t < NB) ? g_blocksum[t] : 0;
    int val = own;
    sh[t] = val;
    __syncthreads();
    for (int d = 1; d < 256; d <<= 1) {
        int a = (t >= d) ? sh[t - d] : 0;
        __syncthreads();
        val += a;
        sh[t] = val;
        __syncthreads();
    }
    if (t < NB) g_blockoff[t] = val - own;
    if (t == NB - 1) g_row_off[NN] = val;
}

__global__ void scanC() {
    int n = blockIdx.x * 256 + threadIdx.x;
    if (n < NN) {
        int off = g_blockoff[blockIdx.x] + g_nodescan[n];
        g_row_off[n] = off;
        g_cursor[n] = off;
    }
}

__global__ void fill_kernel(const int* __restrict__ src, const int* __restrict__ dst,
                            const int* __restrict__ et) {
    int e = blockIdx.x * blockDim.x + threadIdx.x;
    if (e < EE) {
        int d = dst[e];
        int pos = atomicAdd(&g_cursor[d], 1);
        g_adj[pos] = src[e] | (et[e] << 16);
        g_pos[e] = pos;
    }
}

// ---------------- RGCN: warp-per-node gather + per-warp basis GEMM ----------------
template <int IN, int OUT, int WPB>
__global__ __launch_bounds__(32 * WPB) void rgcn_warp(
    const float* __restrict__ x, const float* __restrict__ basis,
    const float* __restrict__ comp, const float* __restrict__ root,
    const float* __restrict__ bias, float* __restrict__ out) {
    const int VW = IN / 32;   // channels per lane
    const int OV = OUT / 32;  // outputs per lane
    __shared__ float zsh[WPB][BB * IN];
    __shared__ float xsh[WPB][IN];
    __shared__ float wsh[WPB][RR * BB];
    int wid = threadIdx.x >> 5, lane = threadIdx.x & 31;
    int n = blockIdx.x * WPB + wid;
    if (n >= NN) return;

    if (lane < RR) {
        float ic = 1.f / fmaxf((float)g_cnt[n * RR + lane], 1.f);
#pragma unroll
        for (int b = 0; b < BB; b++) wsh[wid][lane * BB + b] = comp[lane * BB + b] * ic;
    }
    float xv[VW];
    ldv<VW>(xv, x + (size_t)n * IN + VW * lane);
#pragma unroll
    for (int c = 0; c < VW; c++) xsh[wid][VW * lane + c] = xv[c];
    __syncwarp();

    float acc[BB][VW];
#pragma unroll
    for (int b = 0; b < BB; b++)
#pragma unroll
        for (int c = 0; c < VW; c++) acc[b][c] = 0.f;

    int k1 = g_row_off[n + 1];
    int k = g_row_off[n];
    for (; k + 4 <= k1; k += 4) {
        int v[4];
        float xr[4][VW];
#pragma unroll
        for (int j = 0; j < 4; j++) {
            v[j] = g_adj[k + j];
            ldv<VW>(xr[j], x + (size_t)(v[j] & 0xFFFF) * IN + VW * lane);
        }
#pragma unroll
        for (int j = 0; j < 4; j++) {
            const float* w = &wsh[wid][(v[j] >> 16) * BB];
#pragma unroll
            for (int b = 0; b < BB; b++)
#pragma unroll
                for (int c = 0; c < VW; c++) acc[b][c] += w[b] * xr[j][c];
        }
    }
    for (; k < k1; k++) {
        int v = g_adj[k];
        float xr[VW];
        ldv<VW>(xr, x + (size_t)(v & 0xFFFF) * IN + VW * lane);
        const float* w = &wsh[wid][(v >> 16) * BB];
#pragma unroll
        for (int b = 0; b < BB; b++)
#pragma unroll
            for (int c = 0; c < VW; c++) acc[b][c] += w[b] * xr[c];
    }
#pragma unroll
    for (int b = 0; b < BB; b++)
#pragma unroll
        for (int c = 0; c < VW; c++) zsh[wid][b * IN + VW * lane + c] = acc[b][c];
    __syncwarp();

    float a[OV];
#pragma unroll
    for (int o = 0; o < OV; o++) a[o] = __ldg(bias + OV * lane + o);
    const float* zp = zsh[wid];
#pragma unroll 4
    for (int kk = 0; kk < BB * IN; kk++) {
        float zv = zp[kk];
        if (OV == 2) {
            float2 bv = ld2(basis + (size_t)kk * OUT + 2 * lane);
            a[0] += zv * bv.x;
            a[OV - 1] += zv * bv.y;
        } else {
            a[0] += zv * __ldg(basis + (size_t)kk * OUT + lane);
        }
    }
    const float* xp = xsh[wid];
#pragma unroll 4
    for (int kk = 0; kk < IN; kk++) {
        float xk = xp[kk];
        if (OV == 2) {
            float2 rv = ld2(root + (size_t)kk * OUT + 2 * lane);
            a[0] += xk * rv.x;
            a[OV - 1] += xk * rv.y;
        } else {
            a[0] += xk * __ldg(root + (size_t)kk * OUT + lane);
        }
    }
    if (OV == 2) {
        float2 o;
        o.x = fmaxf(a[0], 0.f);
        o.y = fmaxf(a[OV - 1], 0.f);
        *(float2*)(out + (size_t)n * OUT + 2 * lane) = o;
    } else {
        out[(size_t)n * OUT + lane] = fmaxf(a[0], 0.f);
    }
}

// ---------------- GAT node phase ----------------
template <int IN, int H, int C>
__global__ __launch_bounds__(H * C) void gat_node(
    const float* __restrict__ x, const float* __restrict__ w,
    const float* __restrict__ asrc, const float* __restrict__ adst) {
    const int OUT = H * C;
    __shared__ float xsh[IN];
    __shared__ float hsh[OUT];
    int n = blockIdx.x;
    int t = threadIdx.x;
    for (int i = t; i < IN; i += OUT) xsh[i] = x[(size_t)n * IN + i];
    __syncthreads();
    float a = 0.f;
#pragma unroll 4
    for (int i = 0; i < IN; i++) a += xsh[i] * w[i * OUT + t];
    hsh[t] = a;
    g_h[(size_t)n * OUT + t] = a;
    __syncthreads();
    if (t < 2 * H) {
        int hh = (t < H) ? t : t - H;
        const float* av = (t < H) ? asrc : adst;
        float s = 0.f;
#pragma unroll
        for (int c = 0; c < C; c++) s += hsh[hh * C + c] * av[hh * C + c];
        g_al[n * 2 * H + t] = s;
    }
}

// ---------------- per-edge softmax numerators ----------------
__device__ __forceinline__ float lrexp(float v) {
    v = v > 0.f ? v : 0.2f * v;
    return __expf(v);
}

__global__ void ev_kernel(const int* __restrict__ src, const int* __restrict__ dst) {
    int e = blockIdx.x * blockDim.x + threadIdx.x;
    if (e >= EE) return;
    int s = src[e], d = dst[e], pos = g_pos[e];
    float4 as = *(const float4*)(g_al + (size_t)s * 8);
    float4 ad = *(const float4*)(g_al + (size_t)d * 8 + 4);
    float4 ev;
    ev.x = lrexp(as.x + ad.x);
    ev.y = lrexp(as.y + ad.y);
    ev.z = lrexp(as.z + ad.z);
    ev.w = lrexp(as.w + ad.w);
    *(float4*)(g_ev + (size_t)pos * 4) = ev;
}

// ---------------- GAT gather: warp-per-node, sync-free ----------------
// H=4, C=32, HC=128. Lane owns float4 channels 4*lane.. ; head = lane/8.
template <int WPB>
__global__ __launch_bounds__(32 * WPB) void gat_concat_warp(
    const float* __restrict__ bias, float* __restrict__ out) {
    int wid = threadIdx.x >> 5, lane = threadIdx.x & 31;
    int n = blockIdx.x * WPB + wid;
    if (n >= NN) return;
    int h = lane >> 3;
    float4 acc = make_float4(0.f, 0.f, 0.f, 0.f);
    float z = 0.f;
    int k1 = g_row_off[n + 1];
    int k = g_row_off[n];
    for (; k + 4 <= k1; k += 4) {
        int s0 = g_adj[k + 0] & 0xFFFF, s1 = g_adj[k + 1] & 0xFFFF;
        int s2 = g_adj[k + 2] & 0xFFFF, s3 = g_adj[k + 3] & 0xFFFF;
        float e0 = __ldg(g_ev + (size_t)(k + 0) * 4 + h);
        float e1 = __ldg(g_ev + (size_t)(k + 1) * 4 + h);
        float e2 = __ldg(g_ev + (size_t)(k + 2) * 4 + h);
        float e3 = __ldg(g_ev + (size_t)(k + 3) * 4 + h);
        float4 h0 = ld4(g_h + (size_t)s0 * 128 + 4 * lane);
        float4 h1 = ld4(g_h + (size_t)s1 * 128 + 4 * lane);
        float4 h2 = ld4(g_h + (size_t)s2 * 128 + 4 * lane);
        float4 h3 = ld4(g_h + (size_t)s3 * 128 + 4 * lane);
        z += (e0 + e1) + (e2 + e3);
        acc.x += e0 * h0.x + e1 * h1.x + e2 * h2.x + e3 * h3.x;
        acc.y += e0 * h0.y + e1 * h1.y + e2 * h2.y + e3 * h3.y;
        acc.z += e0 * h0.z + e1 * h1.z + e2 * h2.z + e3 * h3.z;
        acc.w += e0 * h0.w + e1 * h1.w + e2 * h2.w + e3 * h3.w;
    }
    for (; k < k1; k++) {
        int s = g_adj[k] & 0xFFFF;
        float e = __ldg(g_ev + (size_t)k * 4 + h);
        float4 hv = ld4(g_h + (size_t)s * 128 + 4 * lane);
        z += e;
        acc.x += e * hv.x; acc.y += e * hv.y; acc.z += e * hv.z; acc.w += e * hv.w;
    }
    {   // self loop
        float e = lrexp(g_al[(size_t)n * 8 + h] + g_al[(size_t)n * 8 + 4 + h]);
        float4 hv = ld4(g_h + (size_t)n * 128 + 4 * lane);
        z += e;
        acc.x += e * hv.x; acc.y += e * hv.y; acc.z += e * hv.z; acc.w += e * hv.w;
    }
    float inv = 1.f / z;
    float4 b = __ldg((const float4*)bias + lane);
    float4 o;
    o.x = acc.x * inv + b.x;
    o.y = acc.y * inv + b.y;
    o.z = acc.z * inv + b.z;
    o.w = acc.w * inv + b.w;
    ((float4*)out)[(size_t)n * 32 + lane] = o;
}

// H=4, C=16, HC=64. Lane owns float2 channels 2*lane..; head = lane/8.
template <int WPB>
__global__ __launch_bounds__(32 * WPB) void gat_mean_warp(
    const float* __restrict__ bias, float* __restrict__ out) {
    int wid = threadIdx.x >> 5, lane = threadIdx.x & 31;
    int n = blockIdx.x * WPB + wid;
    if (n >= NN) return;
    int h = lane >> 3;
    float ax = 0.f, ay = 0.f, z = 0.f;
    int k1 = g_row_off[n + 1];
    int k = g_row_off[n];
    for (; k + 4 <= k1; k += 4) {
        int s0 = g_adj[k + 0] & 0xFFFF, s1 = g_adj[k + 1] & 0xFFFF;
        int s2 = g_adj[k + 2] & 0xFFFF, s3 = g_adj[k + 3] & 0xFFFF;
        float e0 = __ldg(g_ev + (size_t)(k + 0) * 4 + h);
        float e1 = __ldg(g_ev + (size_t)(k + 1) * 4 + h);
        float e2 = __ldg(g_ev + (size_t)(k + 2) * 4 + h);
        float e3 = __ldg(g_ev + (size_t)(k + 3) * 4 + h);
        float2 h0 = ld2(g_h + (size_t)s0 * 64 + 2 * lane);
        float2 h1 = ld2(g_h + (size_t)s1 * 64 + 2 * lane);
        float2 h2 = ld2(g_h + (size_t)s2 * 64 + 2 * lane);
        float2 h3 = ld2(g_h + (size_t)s3 * 64 + 2 * lane);
        z += (e0 + e1) + (e2 + e3);
        ax += e0 * h0.x + e1 * h1.x + e2 * h2.x + e3 * h3.x;
        ay += e0 * h0.y + e1 * h1.y + e2 * h2.y + e3 * h3.y;
    }
    for (; k < k1; k++) {
        int s = g_adj[k] & 0xFFFF;
        float e = __ldg(g_ev + (size_t)k * 4 + h);
        float2 hv = ld2(g_h + (size_t)s * 64 + 2 * lane);
        z += e;
        ax += e * hv.x;
        ay += e * hv.y;
    }
    {   // self loop
        float e = lrexp(g_al[(size_t)n * 8 + h] + g_al[(size_t)n * 8 + 4 + h]);
        float2 hv = ld2(g_h + (size_t)n * 64 + 2 * lane);
        z += e;
        ax += e * hv.x;
        ay += e * hv.y;
    }
    float inv = 1.f / z;
    float vx = ax * inv, vy = ay * inv;
    // sum over 4 heads: lanes l, l^8, l^16, l^24 hold the same within-head channels
    vx += __shfl_xor_sync(0xffffffffu, vx, 8);
    vy += __shfl_xor_sync(0xffffffffu, vy, 8);
    vx += __shfl_xor_sync(0xffffffffu, vx, 16);
    vy += __shfl_xor_sync(0xffffffffu, vy, 16);
    if (lane < 8) {
        int c = 2 * lane;
        float sx = vx * 0.25f + __ldg(bias + c);
        float sy = vy * 0.25f + __ldg(bias + c + 1);
        sx = fmaxf(sx, 0.f);
        sy = fmaxf(sy, 0.f);
        float2 o;
        o.x = tanhf(sx);
        o.y = tanhf(sy);
        *(float2*)(out + (size_t)n * 16 + c) = o;
    }
}

// ---------------- launch ----------------
extern "C" void kernel_launch(void* const* d_in, const int* in_sizes, int n_in,
                              void* d_out, int out_size) {
    const float* x      = (const float*)d_in[0];
    const int*   ei     = (const int*)d_in[1];
    const int*   et     = (const int*)d_in[2];
    const float* basis1 = (const float*)d_in[3];
    const float* comp1  = (const float*)d_in[4];
    const float* root1  = (const float*)d_in[5];
    const float* brg1   = (const float*)d_in[6];
    const float* wg1    = (const float*)d_in[7];
    const float* asrc1  = (const float*)d_in[8];
    const float* adst1  = (const float*)d_in[9];
    const float* bg1    = (const float*)d_in[10];
    const float* basis2 = (const float*)d_in[11];
    const float* comp2  = (const float*)d_in[12];
    const float* root2  = (const float*)d_in[13];
    const float* brg2   = (const float*)d_in[14];
    const float* wg2    = (const float*)d_in[15];
    const float* asrc2  = (const float*)d_in[16];
    const float* adst2  = (const float*)d_in[17];
    const float* bg2    = (const float*)d_in[18];
    float* out = (float*)d_out;
    const int* src = ei;
    const int* dst = ei + EE;

    int* p_cnt;
    float *p_x1, *p_x2, *p_x3;
    cudaGetSymbolAddress((void**)&p_cnt, g_cnt);
    cudaGetSymbolAddress((void**)&p_x1, g_x1);
    cudaGetSymbolAddress((void**)&p_x2, g_x2);
    cudaGetSymbolAddress((void**)&p_x3, g_x3);

    // --- CSR build ---
    zero_int<<<(NN * RR + 255) / 256, 256>>>(p_cnt, NN * RR);
    hist_kernel<<<(EE + 255) / 256, 256>>>(dst, et);
    scanA<<<NB, 256>>>();
    scanB<<<1, 256>>>();
    scanC<<<NB, 256>>>();
    fill_kernel<<<(EE + 255) / 256, 256>>>(src, dst, et);

    const int WPB = 4;
    int nblk = (NN + WPB - 1) / WPB;

    // ---- RGCN 1: 64 -> 64, relu ----
    rgcn_warp<64, 64, WPB><<<nblk, 32 * WPB>>>(x, basis1, comp1, root1, brg1, p_x1);
    // ---- GAT 1: 64 -> 4x32 concat ----
    gat_node<64, 4, 32><<<NN, 128>>>(p_x1, wg1, asrc1, adst1);
    ev_kernel<<<(EE + 255) / 256, 256>>>(src, dst);
    gat_concat_warp<WPB><<<nblk, 32 * WPB>>>(bg1, p_x2);
    // ---- RGCN 2: 128 -> 32, relu ----
    rgcn_warp<128, 32, WPB><<<nblk, 32 * WPB>>>(p_x2, basis2, comp2, root2, brg2, p_x3);
    // ---- GAT 2: 32 -> 4x16, mean heads, relu, tanh ----
    gat_node<32, 4, 16><<<NN, 64>>>(p_x3, wg2, asrc2, adst2);
    ev_kernel<<<(EE + 255) / 256, 256>>>(src, dst);
    gat_mean_warp<WPB><<<nblk, 32 * WPB>>>(bg2, out);
}

// round 8
// speedup vs baseline: 2.7469x; 1.9856x over previous
#include <cuda_runtime.h>
#include <math.h>

#define NN 50000
#define EE 800000
#define RR 8
#define BB 4
#define NB ((NN + 255) / 256)

// ---------------- scratch (device globals; no allocation) ----------------
__device__ float g_x1[NN * 64];
__device__ float g_x2[NN * 128];
__device__ float g_x3[NN * 32];
__device__ float g_h[NN * 128];
__device__ float g_al[NN * 8];
__device__ float g_z[(size_t)NN * 512];  // B-space aggregates (max 512/node)
__device__ int   g_cnt[NN * RR];
__device__ int   g_row_off[NN + 1];
__device__ int   g_cursor[NN];
__device__ int   g_adj[EE];            // src | (etype<<16)
__device__ int   g_pos[EE];
__device__ float g_ev[(size_t)EE * 4]; // CSR-ordered softmax numerators [pos][4]
__device__ int   g_nodescan[NN];
__device__ int   g_blocksum[NB];
__device__ int   g_blockoff[NB];

__device__ __forceinline__ float4 ld4(const float* p) { return __ldg((const float4*)p); }
__device__ __forceinline__ float2 ld2(const float* p) { return __ldg((const float2*)p); }

template <int VW>
__device__ __forceinline__ void ldv(float (&d)[VW], const float* p) {
    if (VW == 2) {
        float2 v = ld2(p);
        d[0] = v.x; d[1] = v.y;
    } else {
        float4 v = ld4(p);
        d[0] = v.x; d[1] = v.y; d[2] = v.z; d[3] = v.w;
    }
}

// ---------------- CSR build ----------------
__global__ void zero_int(int* __restrict__ p, int n) {
    int i = blockIdx.x * blockDim.x + threadIdx.x;
    if (i < n) p[i] = 0;
}

__global__ void hist_kernel(const int* __restrict__ dst, const int* __restrict__ et) {
    int e = blockIdx.x * blockDim.x + threadIdx.x;
    if (e < EE) atomicAdd(&g_cnt[dst[e] * RR + et[e]], 1);
}

__global__ void scanA() {
    __shared__ int sh[256];
    int t = threadIdx.x;
    int n = blockIdx.x * 256 + t;
    int deg = 0;
    if (n < NN) {
#pragma unroll
        for (int r = 0; r < RR; r++) deg += g_cnt[n * RR + r];
    }
    int val = deg;
    sh[t] = val;
    __syncthreads();
    for (int d = 1; d < 256; d <<= 1) {
        int a = (t >= d) ? sh[t - d] : 0;
        __syncthreads();
        val += a;
        sh[t] = val;
        __syncthreads();
    }
    if (n < NN) g_nodescan[n] = val - deg;
    if (t == 255) g_blocksum[blockIdx.x] = val;
}

__global__ void scanB() {
    __shared__ int sh[256];
    int t = threadIdx.x;
    int own = (t < NB) ? g_blocksum[t] : 0;
    int val = own;
    sh[t] = val;
    __syncthreads();
    for (int d = 1; d < 256; d <<= 1) {
        int a = (t >= d) ? sh[t - d] : 0;
        __syncthreads();
        val += a;
        sh[t] = val;
        __syncthreads();
    }
    if (t < NB) g_blockoff[t] = val - own;
    if (t == NB - 1) g_row_off[NN] = val;
}

__global__ void scanC() {
    int n = blockIdx.x * 256 + threadIdx.x;
    if (n < NN) {
        int off = g_blockoff[blockIdx.x] + g_nodescan[n];
        g_row_off[n] = off;
        g_cursor[n] = off;
    }
}

__global__ void fill_kernel(const int* __restrict__ src, const int* __restrict__ dst,
                            const int* __restrict__ et) {
    int e = blockIdx.x * blockDim.x + threadIdx.x;
    if (e < EE) {
        int d = dst[e];
        int pos = atomicAdd(&g_cursor[d], 1);
        g_adj[pos] = src[e] | (et[e] << 16);
        g_pos[e] = pos;
    }
}

// ---------------- RGCN: warp-per-node gather -> z[n, BB*IN] ----------------
template <int IN, int WPB>
__global__ __launch_bounds__(32 * WPB) void rgcn_gather_z(
    const float* __restrict__ x, const float* __restrict__ comp) {
    const int VW = IN / 32;
    __shared__ float wsh[WPB][RR * BB];
    int wid = threadIdx.x >> 5, lane = threadIdx.x & 31;
    int n = blockIdx.x * WPB + wid;
    if (n >= NN) return;

    if (lane < RR) {
        float ic = 1.f / fmaxf((float)g_cnt[n * RR + lane], 1.f);
#pragma unroll
        for (int b = 0; b < BB; b++) wsh[wid][lane * BB + b] = comp[lane * BB + b] * ic;
    }
    __syncwarp();

    float acc[BB][VW];
#pragma unroll
    for (int b = 0; b < BB; b++)
#pragma unroll
        for (int c = 0; c < VW; c++) acc[b][c] = 0.f;

    int k1 = g_row_off[n + 1];
    int k = g_row_off[n];
    for (; k + 4 <= k1; k += 4) {
        int v[4];
        float xr[4][VW];
#pragma unroll
        for (int j = 0; j < 4; j++) {
            v[j] = g_adj[k + j];
            ldv<VW>(xr[j], x + (size_t)(v[j] & 0xFFFF) * IN + VW * lane);
        }
#pragma unroll
        for (int j = 0; j < 4; j++) {
            const float* w = &wsh[wid][(v[j] >> 16) * BB];
#pragma unroll
            for (int b = 0; b < BB; b++)
#pragma unroll
                for (int c = 0; c < VW; c++) acc[b][c] += w[b] * xr[j][c];
        }
    }
    for (; k < k1; k++) {
        int v = g_adj[k];
        float xr[VW];
        ldv<VW>(xr, x + (size_t)(v & 0xFFFF) * IN + VW * lane);
        const float* w = &wsh[wid][(v >> 16) * BB];
#pragma unroll
        for (int b = 0; b < BB; b++)
#pragma unroll
            for (int c = 0; c < VW; c++) acc[b][c] += w[b] * xr[c];
    }
    float* zp = g_z + (size_t)n * (BB * IN);
#pragma unroll
    for (int b = 0; b < BB; b++) {
        if (VW == 2) {
            float2 o; o.x = acc[b][0]; o.y = acc[b][1];
            *(float2*)(zp + b * IN + 2 * lane) = o;
        } else {
            float4 o; o.x = acc[b][0]; o.y = acc[b][1]; o.z = acc[b][VW - 2]; o.w = acc[b][VW - 1];
            *(float4*)(zp + b * IN + 4 * lane) = o;
        }
    }
}

// ---------------- tiled GEMM: C = A1@W1 + A2@W2 + bias, relu ----------------
template <int K1, int K2, int N, int MT>
__global__ __launch_bounds__(128) void gemm_rgcn(
    const float* __restrict__ A1, const float* __restrict__ A2,
    const float* __restrict__ W1, const float* __restrict__ W2,
    const float* __restrict__ bias, float* __restrict__ C) {
    const int KT = 32;
    const int TX = N / 4, TY = 128 / TX, MR = MT / TY;
    __shared__ float At[MT][KT + 4];
    __shared__ float Wt[KT][N];
    int tid = threadIdx.x;
    int tx = tid % TX, ty = tid / TX;
    int m0 = blockIdx.x * MT;
    float acc[MR][4];
#pragma unroll
    for (int r = 0; r < MR; r++)
        for (int j = 0; j < 4; j++) acc[r][j] = 0.f;

    const int T1 = K1 / KT, T2 = K2 / KT;
    for (int t = 0; t < T1 + T2; t++) {
        const float* A; const float* Wsrc;
        int ks, kstride;
        if (t < T1) { A = A1; ks = t * KT; kstride = K1; Wsrc = W1 + t * KT * N; }
        else        { A = A2; ks = (t - T1) * KT; kstride = K2; Wsrc = W2 + (t - T1) * KT * N; }
        __syncthreads();
        const int FR = KT / 4;
        for (int idx = tid; idx < MT * FR; idx += 128) {
            int m = idx / FR, kq = idx % FR;
            int gm = m0 + m; if (gm >= NN) gm = NN - 1;
            float4 v = ld4(A + (size_t)gm * kstride + ks + 4 * kq);
            *(float4*)&At[m][4 * kq] = v;
        }
        for (int idx = tid; idx < KT * N / 4; idx += 128) {
            int row = idx / (N / 4), cq = idx % (N / 4);
            *(float4*)&Wt[row][4 * cq] = ld4(Wsrc + row * N + 4 * cq);
        }
        __syncthreads();
#pragma unroll
        for (int kk = 0; kk < KT; kk++) {
            float4 wv = *(const float4*)&Wt[kk][tx * 4];
#pragma unroll
            for (int r = 0; r < MR; r++) {
                float av = At[r * TY + ty][kk];
                acc[r][0] += av * wv.x;
                acc[r][1] += av * wv.y;
                acc[r][2] += av * wv.z;
                acc[r][3] += av * wv.w;
            }
        }
    }
    float4 bv = ld4(bias + tx * 4);
#pragma unroll
    for (int r = 0; r < MR; r++) {
        int n = m0 + r * TY + ty;
        if (n < NN) {
            float4 o;
            o.x = fmaxf(acc[r][0] + bv.x, 0.f);
            o.y = fmaxf(acc[r][1] + bv.y, 0.f);
            o.z = fmaxf(acc[r][2] + bv.z, 0.f);
            o.w = fmaxf(acc[r][3] + bv.w, 0.f);
            *(float4*)(C + (size_t)n * N + tx * 4) = o;
        }
    }
}

// ---------------- tiled GEMM for GAT: h = A@W, fused attention logits ----------------
template <int K, int N, int MT, int CH>
__global__ __launch_bounds__(128) void gemm_gat(
    const float* __restrict__ A, const float* __restrict__ W,
    const float* __restrict__ asrc, const float* __restrict__ adst) {
    const int KT = 32;
    const int TX = N / 4, TY = 128 / TX, MR = MT / TY;
    __shared__ float At[MT][KT + 4];
    __shared__ float Wt[KT][N];
    int tid = threadIdx.x;
    int tx = tid % TX, ty = tid / TX;
    int m0 = blockIdx.x * MT;
    float acc[MR][4];
#pragma unroll
    for (int r = 0; r < MR; r++)
        for (int j = 0; j < 4; j++) acc[r][j] = 0.f;

    const int T = K / KT;
    for (int t = 0; t < T; t++) {
        __syncthreads();
        const int FR = KT / 4;
        for (int idx = tid; idx < MT * FR; idx += 128) {
            int m = idx / FR, kq = idx % FR;
            int gm = m0 + m; if (gm >= NN) gm = NN - 1;
            *(float4*)&At[m][4 * kq] = ld4(A + (size_t)gm * K + t * KT + 4 * kq);
        }
        for (int idx = tid; idx < KT * N / 4; idx += 128) {
            int row = idx / (N / 4), cq = idx % (N / 4);
            *(float4*)&Wt[row][4 * cq] = ld4(W + (t * KT + row) * N + 4 * cq);
        }
        __syncthreads();
#pragma unroll
        for (int kk = 0; kk < KT; kk++) {
            float4 wv = *(const float4*)&Wt[kk][tx * 4];
#pragma unroll
            for (int r = 0; r < MR; r++) {
                float av = At[r * TY + ty][kk];
                acc[r][0] += av * wv.x;
                acc[r][1] += av * wv.y;
                acc[r][2] += av * wv.z;
                acc[r][3] += av * wv.w;
            }
        }
    }
    // epilogue: write h, compute per-head logits via shfl reduction
    const int GL = CH / 4;  // lanes per head group
    float4 as = ld4(asrc + tx * 4);
    float4 ad = ld4(adst + tx * 4);
    int head = (tx * 4) / CH;
#pragma unroll
    for (int r = 0; r < MR; r++) {
        int n = m0 + r * TY + ty;
        bool ok = n < NN;
        float4 hv;
        hv.x = acc[r][0]; hv.y = acc[r][1]; hv.z = acc[r][2]; hv.w = acc[r][3];
        if (ok) *(float4*)(g_h + (size_t)n * N + tx * 4) = hv;
        float ps = hv.x * as.x + hv.y * as.y + hv.z * as.z + hv.w * as.w;
        float pd = hv.x * ad.x + hv.y * ad.y + hv.z * ad.z + hv.w * ad.w;
#pragma unroll
        for (int off = 1; off < GL; off <<= 1) {
            ps += __shfl_xor_sync(0xffffffffu, ps, off);
            pd += __shfl_xor_sync(0xffffffffu, pd, off);
        }
        if (ok && (tx % GL) == 0) {
            g_al[n * 8 + head] = ps;
            g_al[n * 8 + 4 + head] = pd;
        }
    }
}

// ---------------- per-edge softmax numerators ----------------
__device__ __forceinline__ float lrexp(float v) {
    v = v > 0.f ? v : 0.2f * v;
    return __expf(v);
}

__global__ void ev_kernel(const int* __restrict__ src, const int* __restrict__ dst) {
    int e = blockIdx.x * blockDim.x + threadIdx.x;
    if (e >= EE) return;
    int s = src[e], d = dst[e], pos = g_pos[e];
    float4 as = *(const float4*)(g_al + (size_t)s * 8);
    float4 ad = *(const float4*)(g_al + (size_t)d * 8 + 4);
    float4 ev;
    ev.x = lrexp(as.x + ad.x);
    ev.y = lrexp(as.y + ad.y);
    ev.z = lrexp(as.z + ad.z);
    ev.w = lrexp(as.w + ad.w);
    *(float4*)(g_ev + (size_t)pos * 4) = ev;
}

// ---------------- GAT gather: warp-per-node, sync-free ----------------
template <int WPB>
__global__ __launch_bounds__(32 * WPB) void gat_concat_warp(
    const float* __restrict__ bias, float* __restrict__ out) {
    int wid = threadIdx.x >> 5, lane = threadIdx.x & 31;
    int n = blockIdx.x * WPB + wid;
    if (n >= NN) return;
    int h = lane >> 3;
    float4 acc = make_float4(0.f, 0.f, 0.f, 0.f);
    float z = 0.f;
    int k1 = g_row_off[n + 1];
    int k = g_row_off[n];
    for (; k + 4 <= k1; k += 4) {
        int s0 = g_adj[k + 0] & 0xFFFF, s1 = g_adj[k + 1] & 0xFFFF;
        int s2 = g_adj[k + 2] & 0xFFFF, s3 = g_adj[k + 3] & 0xFFFF;
        float e0 = __ldg(g_ev + (size_t)(k + 0) * 4 + h);
        float e1 = __ldg(g_ev + (size_t)(k + 1) * 4 + h);
        float e2 = __ldg(g_ev + (size_t)(k + 2) * 4 + h);
        float e3 = __ldg(g_ev + (size_t)(k + 3) * 4 + h);
        float4 h0 = ld4(g_h + (size_t)s0 * 128 + 4 * lane);
        float4 h1 = ld4(g_h + (size_t)s1 * 128 + 4 * lane);
        float4 h2 = ld4(g_h + (size_t)s2 * 128 + 4 * lane);
        float4 h3 = ld4(g_h + (size_t)s3 * 128 + 4 * lane);
        z += (e0 + e1) + (e2 + e3);
        acc.x += e0 * h0.x + e1 * h1.x + e2 * h2.x + e3 * h3.x;
        acc.y += e0 * h0.y + e1 * h1.y + e2 * h2.y + e3 * h3.y;
        acc.z += e0 * h0.z + e1 * h1.z + e2 * h2.z + e3 * h3.z;
        acc.w += e0 * h0.w + e1 * h1.w + e2 * h2.w + e3 * h3.w;
    }
    for (; k < k1; k++) {
        int s = g_adj[k] & 0xFFFF;
        float e = __ldg(g_ev + (size_t)k * 4 + h);
        float4 hv = ld4(g_h + (size_t)s * 128 + 4 * lane);
        z += e;
        acc.x += e * hv.x; acc.y += e * hv.y; acc.z += e * hv.z; acc.w += e * hv.w;
    }
    {   // self loop
        float e = lrexp(g_al[(size_t)n * 8 + h] + g_al[(size_t)n * 8 + 4 + h]);
        float4 hv = ld4(g_h + (size_t)n * 128 + 4 * lane);
        z += e;
        acc.x += e * hv.x; acc.y += e * hv.y; acc.z += e * hv.z; acc.w += e * hv.w;
    }
    float inv = 1.f / z;
    float4 b = __ldg((const float4*)bias + lane);
    float4 o;
    o.x = acc.x * inv + b.x;
    o.y = acc.y * inv + b.y;
    o.z = acc.z * inv + b.z;
    o.w = acc.w * inv + b.w;
    ((float4*)out)[(size_t)n * 32 + lane] = o;
}

template <int WPB>
__global__ __launch_bounds__(32 * WPB) void gat_mean_warp(
    const float* __restrict__ bias, float* __restrict__ out) {
    int wid = threadIdx.x >> 5, lane = threadIdx.x & 31;
    int n = blockIdx.x * WPB + wid;
    if (n >= NN) return;
    int h = lane >> 3;
    float ax = 0.f, ay = 0.f, z = 0.f;
    int k1 = g_row_off[n + 1];
    int k = g_row_off[n];
    for (; k + 4 <= k1; k += 4) {
        int s0 = g_adj[k + 0] & 0xFFFF, s1 = g_adj[k + 1] & 0xFFFF;
        int s2 = g_adj[k + 2] & 0xFFFF, s3 = g_adj[k + 3] & 0xFFFF;
        float e0 = __ldg(g_ev + (size_t)(k + 0) * 4 + h);
        float e1 = __ldg(g_ev + (size_t)(k + 1) * 4 + h);
        float e2 = __ldg(g_ev + (size_t)(k + 2) * 4 + h);
        float e3 = __ldg(g_ev + (size_t)(k + 3) * 4 + h);
        float2 h0 = ld2(g_h + (size_t)s0 * 64 + 2 * lane);
        float2 h1 = ld2(g_h + (size_t)s1 * 64 + 2 * lane);
        float2 h2 = ld2(g_h + (size_t)s2 * 64 + 2 * lane);
        float2 h3 = ld2(g_h + (size_t)s3 * 64 + 2 * lane);
        z += (e0 + e1) + (e2 + e3);
        ax += e0 * h0.x + e1 * h1.x + e2 * h2.x + e3 * h3.x;
        ay += e0 * h0.y + e1 * h1.y + e2 * h2.y + e3 * h3.y;
    }
    for (; k < k1; k++) {
        int s = g_adj[k] & 0xFFFF;
        float e = __ldg(g_ev + (size_t)k * 4 + h);
        float2 hv = ld2(g_h + (size_t)s * 64 + 2 * lane);
        z += e;
        ax += e * hv.x;
        ay += e * hv.y;
    }
    {   // self loop
        float e = lrexp(g_al[(size_t)n * 8 + h] + g_al[(size_t)n * 8 + 4 + h]);
        float2 hv = ld2(g_h + (size_t)n * 64 + 2 * lane);
        z += e;
        ax += e * hv.x;
        ay += e * hv.y;
    }
    float inv = 1.f / z;
    float vx = ax * inv, vy = ay * inv;
    vx += __shfl_xor_sync(0xffffffffu, vx, 8);
    vy += __shfl_xor_sync(0xffffffffu, vy, 8);
    vx += __shfl_xor_sync(0xffffffffu, vx, 16);
    vy += __shfl_xor_sync(0xffffffffu, vy, 16);
    if (lane < 8) {
        int c = 2 * lane;
        float sx = vx * 0.25f + __ldg(bias + c);
        float sy = vy * 0.25f + __ldg(bias + c + 1);
        sx = fmaxf(sx, 0.f);
        sy = fmaxf(sy, 0.f);
        float2 o;
        o.x = tanhf(sx);
        o.y = tanhf(sy);
        *(float2*)(out + (size_t)n * 16 + c) = o;
    }
}

// ---------------- launch ----------------
extern "C" void kernel_launch(void* const* d_in, const int* in_sizes, int n_in,
                              void* d_out, int out_size) {
    const float* x      = (const float*)d_in[0];
    const int*   ei     = (const int*)d_in[1];
    const int*   et     = (const int*)d_in[2];
    const float* basis1 = (const float*)d_in[3];
    const float* comp1  = (const float*)d_in[4];
    const float* root1  = (const float*)d_in[5];
    const float* brg1   = (const float*)d_in[6];
    const float* wg1    = (const float*)d_in[7];
    const float* asrc1  = (const float*)d_in[8];
    const float* adst1  = (const float*)d_in[9];
    const float* bg1    = (const float*)d_in[10];
    const float* basis2 = (const float*)d_in[11];
    const float* comp2  = (const float*)d_in[12];
    const float* root2  = (const float*)d_in[13];
    const float* brg2   = (const float*)d_in[14];
    const float* wg2    = (const float*)d_in[15];
    const float* asrc2  = (const float*)d_in[16];
    const float* adst2  = (const float*)d_in[17];
    const float* bg2    = (const float*)d_in[18];
    float* out = (float*)d_out;
    const int* src = ei;
    const int* dst = ei + EE;

    int* p_cnt;
    float *p_x1, *p_x2, *p_x3, *p_z;
    cudaGetSymbolAddress((void**)&p_cnt, g_cnt);
    cudaGetSymbolAddress((void**)&p_x1, g_x1);
    cudaGetSymbolAddress((void**)&p_x2, g_x2);
    cudaGetSymbolAddress((void**)&p_x3, g_x3);
    cudaGetSymbolAddress((void**)&p_z, g_z);

    // --- CSR build ---
    zero_int<<<(NN * RR + 255) / 256, 256>>>(p_cnt, NN * RR);
    hist_kernel<<<(EE + 255) / 256, 256>>>(dst, et);
    scanA<<<NB, 256>>>();
    scanB<<<1, 256>>>();
    scanC<<<NB, 256>>>();
    fill_kernel<<<(EE + 255) / 256, 256>>>(src, dst, et);

    const int WPB = 4;
    int nblk = (NN + WPB - 1) / WPB;

    // ---- RGCN 1: 64 -> 64, relu ----
    rgcn_gather_z<64, WPB><<<nblk, 32 * WPB>>>(x, comp1);
    gemm_rgcn<256, 64, 64, 128><<<(NN + 127) / 128, 128>>>(p_z, x, basis1, root1, brg1, p_x1);
    // ---- GAT 1: 64 -> 4x32 concat ----
    gemm_gat<64, 128, 64, 32><<<(NN + 63) / 64, 128>>>(p_x1, wg1, asrc1, adst1);
    ev_kernel<<<(EE + 255) / 256, 256>>>(src, dst);
    gat_concat_warp<WPB><<<nblk, 32 * WPB>>>(bg1, p_x2);
    // ---- RGCN 2: 128 -> 32, relu ----
    rgcn_gather_z<128, WPB><<<nblk, 32 * WPB>>>(p_x2, comp2);
    gemm_rgcn<512, 128, 32, 128><<<(NN + 127) / 128, 128>>>(p_z, p_x2, basis2, root2, brg2, p_x3);
    // ---- GAT 2: 32 -> 4x16, mean heads, relu, tanh ----
    gemm_gat<32, 64, 128, 16><<<(NN + 127) / 128, 128>>>(p_x3, wg2, asrc2, adst2);
    ev_kernel<<<(EE + 255) / 256, 256>>>(src, dst);
    gat_mean_warp<WPB><<<nblk, 32 * WPB>>>(bg2, out);
}